// round 15
// baseline (speedup 1.0000x reference)
#include <cuda_runtime.h>
#include <cstdint>
#include <math.h>

#define NEG_INF   (-3.4028234663852886e38f)
#define NBINS     4096
#define CAPA      2048
#define CAPB      1024
#define CAPP      4096
#define CAPC      4096
#define CAPBC     2048
#define SPLIT     4
#define NT1       512
#define NT2       1024
#define MAXCTAS   1024
#define MAXCAND   (SPLIT * CAPA)   // 8192
#define MAXCANDB  (SPLIT * CAPB)   // 4096

// cross-kernel scratch (static __device__ — allocation-free)
__device__ float g_expsum[MAXCTAS];
__device__ int   g_nA[MAXCTAS];
__device__ int   g_nB[MAXCTAS];
__device__ int   g_edgeA[MAXCTAS];
__device__ int   g_edgeB[MAXCTAS];
__device__ unsigned long long g_candA[(size_t)MAXCTAS * CAPA];
__device__ unsigned long long g_candB[(size_t)MAXCTAS * CAPB];

// monotone float <-> uint32 mapping (total order)
__device__ __forceinline__ uint32_t fmap(float f) {
  uint32_t u = __float_as_uint(f);
  return u ^ ((u & 0x80000000u) ? 0xFFFFFFFFu : 0x80000000u);
}
__device__ __forceinline__ float funmap(uint32_t u) {
  uint32_t b = (u & 0x80000000u) ? (u ^ 0x80000000u) : ~u;
  return __uint_as_float(b);
}

struct Ctl1 {
  float rep, rcpRep, rcpTemp, freq, pres;
  int   nStop, hasStop;
  int   stop[8];
  int   kk, mnl;
  int   binSel, nA, nB, nPend;
  uint32_t thrA;
  float tBf, tRejf;
  float red[32];
  uint32_t chunk[64];
};

__device__ __forceinline__ float proc_cp(float raw, int v, int cnt, int pb, const Ctl1& s) {
  float x = raw;
  if (s.hasStop) {
#pragma unroll
    for (int i = 0; i < 8; i++)
      if (i < s.nStop && v == s.stop[i]) x = NEG_INF;
  }
  bool outm = cnt > 0;
  bool seen = outm || (pb != 0);
  float scale = seen ? ((x > 0.0f) ? s.rcpRep : s.rep) : 1.0f;
  x = x * scale;
  x = x - s.freq * (float)cnt;
  if (outm) x = x - s.pres;
  return x * s.rcpTemp;
}

// largest bin beta with (#subset elements in bins >= beta) >= need
template<typename CTL>
__device__ int select_bin(const uint32_t* hist, int need, CTL& s) {
  if (threadIdx.x < 64) {
    uint32_t sum = 0;
    int base = (int)threadIdx.x << 6;
    for (int i = 0; i < 64; i++) sum += hist[base + i];
    s.chunk[threadIdx.x] = sum;
  }
  __syncthreads();
  if (threadIdx.x == 0) {
    long long acc = 0;
    int bin = 0;
    for (int c = 63; c >= 0; c--) {
      long long nacc = acc + (long long)s.chunk[c];
      if (nacc >= need) {
        long long a2 = acc;
        bin = c << 6;
        for (int bi = (c << 6) + 63; bi >= (c << 6); bi--) {
          a2 += (long long)hist[bi];
          if (a2 >= need) { bin = bi; break; }
        }
        break;
      }
      acc = nacc;
    }
    s.binSel = bin;
  }
  __syncthreads();
  return s.binSel;
}

template<int NT>
__device__ void bitonic_desc(unsigned long long* a, int n) {
  for (int k = 2; k <= n; k <<= 1) {
    for (int j = k >> 1; j > 0; j >>= 1) {
      __syncthreads();
      for (int i = (int)threadIdx.x; i < n; i += NT) {
        int l = i ^ j;
        if (l > i) {
          unsigned long long ai = a[i], al = a[l];
          bool descSeg = ((i & k) == 0);
          bool doSwap = descSeg ? (ai < al) : (ai > al);
          if (doSwap) { a[i] = al; a[l] = ai; }
        }
      }
    }
  }
  __syncthreads();
}

// Threefry-2x32-20, JAX partitionable counter mode, key (0,42); out = out0^out1.
__device__ __forceinline__ float gumbel_jax(uint32_t idx) {
  uint32_t x0 = 0u, x1 = idx;
  const uint32_t k0 = 0u, k1 = 42u;
  const uint32_t k2 = k0 ^ k1 ^ 0x1BD11BDAu;
  x0 += k0; x1 += k1;
#define TFR(r) { x0 += x1; x1 = __funnelshift_l(x1, x1, (r)); x1 ^= x0; }
  TFR(13) TFR(15) TFR(26) TFR(6)   x0 += k1; x1 += k2 + 1u;
  TFR(17) TFR(29) TFR(16) TFR(24)  x0 += k2; x1 += k0 + 2u;
  TFR(13) TFR(15) TFR(26) TFR(6)   x0 += k0; x1 += k1 + 3u;
  TFR(17) TFR(29) TFR(16) TFR(24)  x0 += k1; x1 += k2 + 4u;
  TFR(13) TFR(15) TFR(26) TFR(6)   x0 += k2; x1 += k0 + 5u;
#undef TFR
  uint32_t bits = x0 ^ x1;
  float x = __uint_as_float((bits >> 9) | 0x3F800000u) - 1.0f;
  float u = fmaxf(1e-10f, x + 1e-10f);
  return -logf(-logf(u));
}

// ============================================================================
// Kernel 1: per quarter-row (R13 + edge exports)
// ============================================================================
__global__ __launch_bounds__(NT1, 2)
void sampler_pass1(const float* __restrict__ logits,
                   const float* __restrict__ temperature,
                   const float* __restrict__ presence,
                   const float* __restrict__ frequency,
                   const float* __restrict__ repetition,
                   const int*   __restrict__ prompt_ids,
                   const int*   __restrict__ output_ids,
                   const int*   __restrict__ output_lens,
                   const int*   __restrict__ stop_ids,
                   const int*   __restrict__ min_tokens,
                   const int*   __restrict__ top_k,
                   const int*   __restrict__ mnl_ptr,
                   int B, int V, int P, int O, int nStopIn) {
  extern __shared__ uint32_t dsm[];
  __shared__ Ctl1 s;

  const int cta  = blockIdx.x;
  const int b    = cta / SPLIT;
  const int h    = cta % SPLIT;
  const int tid  = (int)threadIdx.x;
  const int lane = tid & 31;
  const int wid  = tid >> 5;

  const int nF4 = V >> 2;
  const int nQ  = nF4 / SPLIT;
  const int qLo = h * nQ;
  const int qHi = (h == SPLIT - 1) ? nF4 : qLo + nQ;
  const int nQl = qHi - qLo;
  const int vLo = qLo << 2;
  const int vHi = (h == SPLIT - 1) ? V : (qHi << 2);
  const int nTok = vHi - vLo;

  const int cntWords = (nTok + 3) >> 2;
  const int pbW      = (nTok + 31) >> 5;
  uint32_t* cntW  = dsm;
  uint32_t* pbits = cntW + cntWords;
  uint32_t* histR = pbits + pbW;
  uint32_t* histP = histR + NBINS;
  int wordsBefore = cntWords + pbW + 2 * NBINS;
  if (wordsBefore & 1) wordsBefore++;
  unsigned long long* candA = (unsigned long long*)(dsm + wordsBefore);
  unsigned long long* candB = candA + CAPA;
  uint32_t* pend = histP;

  for (int i = tid; i < cntWords; i += NT1) cntW[i] = 0u;
  for (int i = tid; i < pbW;      i += NT1) pbits[i] = 0u;
  for (int i = tid; i < NBINS;    i += NT1) { histP[i] = 0u; histR[i] = 0u; }
  if (tid == 0) {
    s.nA = 0; s.nB = 0; s.nPend = 0;
    float temp = temperature[b];
    float tempEff = (temp < 1e-5f) ? 1.0f : temp;
    s.rep    = repetition[b];
    s.rcpRep = 1.0f / s.rep;
    s.rcpTemp = 1.0f / tempEff;
    s.freq = frequency[b];
    s.pres = presence[b];
    int ol  = output_lens[b];
    int pen = (ol < min_tokens[b]) ? 1 : 0;
    int ns  = nStopIn > 8 ? 8 : nStopIn;
    s.nStop   = ns;
    s.hasStop = (pen && ns > 0) ? 1 : 0;
    for (int i = 0; i < ns; i++) s.stop[i] = pen ? stop_ids[b * nStopIn + i] : -1;
    s.kk  = top_k[b];
    s.mnl = mnl_ptr ? mnl_ptr[0] : 20;
  }
  __syncthreads();

  for (int i = tid; i < P; i += NT1) {
    int t = prompt_ids[(size_t)b * P + i];
    if (t >= vLo && t < vHi) {
      int tl = t - vLo;
      atomicOr(&pbits[tl >> 5], 1u << (tl & 31));
    }
  }
  {
    int ol = output_lens[b];
    for (int i = tid; i < O; i += NT1) {
      if (i < ol) {
        int t = output_ids[(size_t)b * O + i];
        if (t >= vLo && t < vHi) {
          int tl = t - vLo;
          atomicAdd(&cntW[tl >> 2], 1u << ((tl & 3) * 8));
        }
      }
    }
  }
  __syncthreads();

  const float* rowL = logits + (size_t)b * V;
  const float4* row4 = (const float4*)rowL;
  int CH = nQl >> 3;
  if (CH < 1) CH = nQl;
  float a0 = 0.f, a1 = 0.f, a2 = 0.f, a3 = 0.f;
  float b0 = 0.f, b1 = 0.f, b2 = 0.f, b3 = 0.f;

  for (int jl = tid; jl < CH; jl += NT1) {
    float4 f = row4[qLo + jl];
    a0 += __expf(f.x); a1 += __expf(f.y);
    a2 += __expf(f.z); a3 += __expf(f.w);
    uint32_t cw = cntW[jl];
    uint32_t pw = pbits[jl >> 3];
    float vals[4] = {f.x, f.y, f.z, f.w};
#pragma unroll
    for (int q = 0; q < 4; q++) {
      int v = ((qLo + jl) << 2) + q;
      int cnt = (int)((cw >> (q * 8)) & 0xFFu);
      int pb  = (int)((pw >> (((jl & 7) << 2) + q)) & 1u);
      float px = proc_cp(vals[q], v, cnt, pb, s);
      atomicAdd(&histR[fmap(vals[q]) >> 20], 1u);
      atomicAdd(&histP[fmap(px)      >> 20], 1u);
    }
  }
  __syncthreads();

  int kneed = s.kk; if (kneed < 1) kneed = 1; if (kneed > V) kneed = V;
  int binA = select_bin(histP, kneed, s);
  int mnl  = s.mnl;
  int binR = select_bin(histR, mnl, s);

  if (tid == 0) {
    s.thrA = (uint32_t)binA << 20;
    s.tBf  = funmap((uint32_t)binR << 20);
    float tA = funmap(s.thrA);
    float rejf = -INFINITY;
    if (tA > 0.0f && s.rep >= 1.0f && s.freq >= 0.0f && s.pres >= 0.0f) {
      float tempEff = 1.0f / s.rcpTemp;
      float rr = tA * tempEff * 0.99f;
      if (rr > 0.0f) rejf = rr;
    }
    s.tRejf = rejf;
  }
  __syncthreads();
  const float tBf   = s.tBf;
  const float tRejf = s.tRejf;
  const float tMin  = fminf(tBf, tRejf);
  uint32_t thrA = s.thrA;

  auto check4 = [&](float4 f, int jl) {
    float vals[4] = {f.x, f.y, f.z, f.w};
#pragma unroll
    for (int q = 0; q < 4; q++) {
      float raw = vals[q];
      int v = ((qLo + jl) << 2) + q;
      if (raw >= tBf) {
        int p = atomicAdd(&s.nB, 1);
        if (p < CAPB) candB[p] = ((unsigned long long)fmap(raw) << 32) | (uint32_t)(~(uint32_t)v);
      }
      if (raw >= tRejf) {
        uint32_t cw = cntW[jl];
        uint32_t pw = pbits[jl >> 3];
        int cnt = (int)((cw >> (q * 8)) & 0xFFu);
        int pb  = (int)((pw >> (((jl & 7) << 2) + q)) & 1u);
        float px = proc_cp(raw, v, cnt, pb, s);
        uint32_t mp = fmap(px);
        if (mp >= thrA) {
          int p = atomicAdd(&s.nA, 1);
          if (p < CAPA) candA[p] = ((unsigned long long)mp << 32) | (uint32_t)(~(uint32_t)v);
        }
      }
    }
  };
  auto push_pend = [&](float4 f, int jl) {
    int p = atomicAdd(&s.nPend, 1);
    if (p < CAPP) pend[p] = (uint32_t)jl;
    else          check4(f, jl);
  };

  int jl = CH + tid;
  for (; jl + 3 * NT1 < nQl; jl += 4 * NT1) {
    float4 f0 = row4[qLo + jl];
    float4 f1 = row4[qLo + jl + NT1];
    float4 f2 = row4[qLo + jl + 2 * NT1];
    float4 f3 = row4[qLo + jl + 3 * NT1];
    a0 += __expf(f0.x); a1 += __expf(f0.y); a2 += __expf(f0.z); a3 += __expf(f0.w);
    b0 += __expf(f1.x); b1 += __expf(f1.y); b2 += __expf(f1.z); b3 += __expf(f1.w);
    a0 += __expf(f2.x); a1 += __expf(f2.y); a2 += __expf(f2.z); a3 += __expf(f2.w);
    b0 += __expf(f3.x); b1 += __expf(f3.y); b2 += __expf(f3.z); b3 += __expf(f3.w);
    float mx0 = fmaxf(fmaxf(f0.x, f0.y), fmaxf(f0.z, f0.w));
    float mx1 = fmaxf(fmaxf(f1.x, f1.y), fmaxf(f1.z, f1.w));
    float mx2 = fmaxf(fmaxf(f2.x, f2.y), fmaxf(f2.z, f2.w));
    float mx3 = fmaxf(fmaxf(f3.x, f3.y), fmaxf(f3.z, f3.w));
    if (mx0 >= tMin) push_pend(f0, jl);
    if (mx1 >= tMin) push_pend(f1, jl + NT1);
    if (mx2 >= tMin) push_pend(f2, jl + 2 * NT1);
    if (mx3 >= tMin) push_pend(f3, jl + 3 * NT1);
  }
  for (; jl < nQl; jl += NT1) {
    float4 f = row4[qLo + jl];
    a0 += __expf(f.x); a1 += __expf(f.y);
    a2 += __expf(f.z); a3 += __expf(f.w);
    float mx = fmaxf(fmaxf(f.x, f.y), fmaxf(f.z, f.w));
    if (mx >= tMin) push_pend(f, jl);
  }
  for (int jc = tid; jc < CH; jc += NT1) {
    float4 f = row4[qLo + jc];
    float mx = fmaxf(fmaxf(f.x, f.y), fmaxf(f.z, f.w));
    if (mx >= tMin) push_pend(f, jc);
  }
  for (int v = (qHi << 2) + tid; v < vHi; v += NT1) {
    float raw = rowL[v];
    a0 += __expf(raw);
    int tl = v - vLo;
    if (raw >= tBf) {
      int p = atomicAdd(&s.nB, 1);
      if (p < CAPB) candB[p] = ((unsigned long long)fmap(raw) << 32) | (uint32_t)(~(uint32_t)v);
    }
    if (raw >= tRejf) {
      uint32_t cw = cntW[tl >> 2];
      uint32_t pw = pbits[tl >> 5];
      int cnt = (int)((cw >> ((tl & 3) * 8)) & 0xFFu);
      int pb  = (int)((pw >> (tl & 31)) & 1u);
      float px = proc_cp(raw, v, cnt, pb, s);
      uint32_t mp = fmap(px);
      if (mp >= thrA) {
        int p = atomicAdd(&s.nA, 1);
        if (p < CAPA) candA[p] = ((unsigned long long)mp << 32) | (uint32_t)(~(uint32_t)v);
      }
    }
  }
  __syncthreads();

  {
    int np = s.nPend < CAPP ? s.nPend : CAPP;
    for (int i = tid; i < np; i += NT1) {
      int jj = (int)pend[i];
      check4(row4[qLo + jj], jj);
    }
  }

  {
    float sl = ((a0 + a1) + (a2 + a3)) + ((b0 + b1) + (b2 + b3));
    for (int off = 16; off; off >>= 1) sl += __shfl_down_sync(0xFFFFFFFFu, sl, off);
    if (lane == 0) s.red[wid] = sl;
  }
  __syncthreads();
  if (wid == 0) {
    float t2 = (lane < (NT1 / 32)) ? s.red[lane] : 0.0f;
    for (int off = 16; off; off >>= 1) t2 += __shfl_down_sync(0xFFFFFFFFu, t2, off);
    if (lane == 0) g_expsum[cta] = t2;
  }
  __syncthreads();

  while (s.nA > CAPA) {
    __syncthreads();
    if (tid == 0) { binA = binA < 4095 ? binA + 1 : 4095; s.thrA = (uint32_t)binA << 20; s.nA = 0; }
    __syncthreads();
    binA = (int)(s.thrA >> 20);
    thrA = s.thrA;
    for (int v = vLo + tid; v < vHi; v += NT1) {
      float raw = rowL[v];
      if (raw >= tRejf) {
        int tl = v - vLo;
        uint32_t cw = cntW[tl >> 2];
        uint32_t pw = pbits[tl >> 5];
        int cnt = (int)((cw >> ((tl & 3) * 8)) & 0xFFu);
        int pb  = (int)((pw >> (tl & 31)) & 1u);
        float px = proc_cp(raw, v, cnt, pb, s);
        uint32_t mp = fmap(px);
        if (mp >= thrA) {
          int p = atomicAdd(&s.nA, 1);
          if (p < CAPA) candA[p] = ((unsigned long long)mp << 32) | (uint32_t)(~(uint32_t)v);
        }
      }
    }
    __syncthreads();
    if (binA >= 4095) break;
  }
  __syncthreads();

  int nAc = s.nA < CAPA ? s.nA : CAPA;
  int nBc = s.nB < CAPB ? s.nB : CAPB;
  if (tid == 0) {
    g_nA[cta] = nAc; g_nB[cta] = nBc;
    g_edgeA[cta] = (int)(s.thrA >> 20);   // final (possibly tightened) bin edge
    g_edgeB[cta] = binR;
  }
  for (int i = tid; i < nAc; i += NT1) g_candA[(size_t)cta * CAPA + i] = candA[i];
  for (int i = tid; i < nBc; i += NT1) g_candB[(size_t)cta * CAPB + i] = candB[i];
}

// ============================================================================
// Kernel 2: per row — max-edge compaction, small sorts, epilogue, outputs
// ============================================================================
struct Ctl2 {
  float temp, topp, Ssum, lse;
  int   kk, mnl, nAtot, nBtot, mCount;
  int   nC, nBc2, maxEA, maxEB;
  unsigned long long bestKey;
  float red[32];
  int   na[SPLIT], nb[SPLIT];
};

__global__ __launch_bounds__(NT2, 1)
void sampler_pass2(const float* __restrict__ temperature,
                   const float* __restrict__ top_p,
                   const int*   __restrict__ top_k,
                   const int*   __restrict__ mnl_ptr,
                   float*       __restrict__ out,
                   int B, int V) {
  extern __shared__ uint32_t dsm[];
  __shared__ Ctl2 s;

  const int b    = blockIdx.x;
  const int base = b * SPLIT;
  const int tid  = (int)threadIdx.x;
  const int lane = tid & 31;
  const int wid  = tid >> 5;

  unsigned long long* candM  = (unsigned long long*)dsm;   // MAXCAND  (A fallback / eArr scratch)
  unsigned long long* candC  = candM + MAXCAND;            // CAPC     (A compact)
  unsigned long long* candBc = candC + CAPC;               // CAPBC    (B compact)

  if (tid == 0) {
    int oa = 0, ob = 0, ea = -1, eb = -1;
    for (int i = 0; i < SPLIT; i++) {
      s.na[i] = g_nA[base + i]; oa += s.na[i];
      s.nb[i] = g_nB[base + i]; ob += s.nb[i];
      int e1 = g_edgeA[base + i]; if (e1 > ea) ea = e1;
      int e2 = g_edgeB[base + i]; if (e2 > eb) eb = e2;
    }
    s.nAtot = oa; s.nBtot = ob; s.maxEA = ea; s.maxEB = eb;
    s.nC = 0; s.nBc2 = 0;
    float es = 0.0f;
    for (int i = 0; i < SPLIT; i++) es += g_expsum[base + i];
    s.lse  = logf(es);
    s.temp = temperature[b];
    s.topp = top_p[b];
    s.kk   = top_k[b];
    s.mnl  = mnl_ptr ? mnl_ptr[0] : 20;
    s.bestKey = 0ull;
  }
  __syncthreads();
  const int mnl = s.mnl;
  int kneed = s.kk; if (kneed < 1) kneed = 1; if (kneed > V) kneed = V;
  const uint32_t eA = (uint32_t)s.maxEA;
  const uint32_t eB = (uint32_t)s.maxEB;

  // ---- compact with max-edge predicate (reads straight from global) ----
  for (int i = 0; i < SPLIT; i++) {
    int n = s.na[i];
    const unsigned long long* src = &g_candA[(size_t)(base + i) * CAPA];
    for (int idx = tid; idx < n; idx += NT2) {
      unsigned long long key = src[idx];
      if ((uint32_t)(key >> 52) >= eA) {
        int p = atomicAdd(&s.nC, 1);
        if (p < CAPC) candC[p] = key;
      }
    }
  }
  for (int i = 0; i < SPLIT; i++) {
    int n = s.nb[i];
    const unsigned long long* src = &g_candB[(size_t)(base + i) * CAPB];
    for (int idx = tid; idx < n; idx += NT2) {
      unsigned long long key = src[idx];
      if ((uint32_t)(key >> 52) >= eB) {
        int p = atomicAdd(&s.nBc2, 1);
        if (p < CAPBC) candBc[p] = key;
      }
    }
  }
  __syncthreads();
  int nC   = s.nC;
  int nBc2 = s.nBc2;
  int nBneed = mnl < s.nBtot ? mnl : s.nBtot;
  bool fullA = (nC > CAPC) || (nC < (kneed < s.nAtot ? kneed : s.nAtot));
  bool fullB = (nBc2 > CAPBC) || (nBc2 < nBneed);

  // ---- B side: sort + emit outputs 1 & 2 ----
  {
    unsigned long long* bs; int nb2;
    if (fullB) {  // fallback: gather all B into candM (A sort happens later)
      unsigned long long* dst = candM;
      int off = 0;
      for (int i = 0; i < SPLIT; i++) {
        int n = s.nb[i];
        const unsigned long long* src = &g_candB[(size_t)(base + i) * CAPB];
        for (int idx = tid; idx < n; idx += NT2) dst[off + idx] = src[idx];
        off += n;
      }
      bs = dst; nb2 = s.nBtot;
      if (nb2 < 1) nb2 = 1;
      int sortN = 2; while (sortN < nb2) sortN <<= 1;
      if (sortN > MAXCANDB) sortN = MAXCANDB;
      for (int i = nb2 + tid; i < sortN; i += NT2) bs[i] = 0ull;
      __syncthreads();
      bitonic_desc<NT2>(bs, sortN);
    } else {
      bs = candBc; nb2 = nBc2;
      if (nb2 < 1) nb2 = 1;
      int sortN = 2; while (sortN < nb2) sortN <<= 1;
      for (int i = nb2 + tid; i < sortN; i += NT2) bs[i] = 0ull;
      __syncthreads();
      bitonic_desc<NT2>(bs, sortN);
    }
    int lim = nb2 < s.nBtot ? nb2 : s.nBtot;
    for (int j = tid; j < mnl; j += NT2) {
      float val; int v;
      if (j < lim) {
        unsigned long long key = bs[j];
        v   = (int)(~(uint32_t)(key & 0xFFFFFFFFull));
        val = funmap((uint32_t)(key >> 32));
      } else { v = 0; val = NEG_INF; }
      out[(size_t)B + (size_t)b * mnl + j]                   = val - s.lse;
      out[(size_t)B + (size_t)B * mnl + (size_t)b * mnl + j] = (float)v;
    }
  }
  __syncthreads();

  // ---- A side: sort active set ----
  unsigned long long* act;
  int nAct;
  if (fullA) {
    int off = 0;
    for (int i = 0; i < SPLIT; i++) {
      int n = s.na[i];
      const unsigned long long* src = &g_candA[(size_t)(base + i) * CAPA];
      for (int idx = tid; idx < n; idx += NT2) candM[off + idx] = src[idx];
      off += n;
    }
    act = candM; nAct = s.nAtot;
    if (nAct < 1) nAct = 1;
    int sortN = 2; while (sortN < nAct) sortN <<= 1;
    if (sortN > MAXCAND) sortN = MAXCAND;
    for (int i = nAct + tid; i < sortN; i += NT2) candM[i] = 0ull;
    __syncthreads();
    bitonic_desc<NT2>(candM, sortN);
  } else {
    act = candC; nAct = nC;
    if (nAct < 1) nAct = 1;
    int sortN = 2; while (sortN < nAct) sortN <<= 1;
    for (int i = nAct + tid; i < sortN; i += NT2) candC[i] = 0ull;
    __syncthreads();
    bitonic_desc<NT2>(candC, sortN);
  }

  // ---- top-k boundary + survivor count ----
  if (tid == 0) {
    int k = kneed; if (k > nAct) k = nAct; if (k < 1) k = 1;
    uint32_t kth = (uint32_t)(act[k - 1] >> 32);
    int m = k;
    while (m < nAct && (uint32_t)(act[m] >> 32) >= kth) m++;
    if (m > CAPC) m = CAPC;
    s.mCount = m;
  }
  __syncthreads();
  const int m = s.mCount;
  const float maxV = funmap((uint32_t)(act[0] >> 32));

  float*    eArr    = fullA ? (float*)candC : (float*)candM;
  uint32_t* keepArr = (fullA ? (uint32_t*)candC : (uint32_t*)candM) + CAPC;

  // ---- softmax over survivors ----
  float local = 0.0f;
  for (int jj = tid; jj < m; jj += NT2) {
    float vj = funmap((uint32_t)(act[jj] >> 32));
    float e  = expf(vj - maxV);
    eArr[jj] = e;
    local += e;
  }
  for (int off = 16; off; off >>= 1) local += __shfl_down_sync(0xFFFFFFFFu, local, off);
  if (lane == 0) s.red[wid] = local;
  __syncthreads();
  if (wid == 0) {
    float t2 = s.red[lane];
    for (int off = 16; off; off >>= 1) t2 += __shfl_down_sync(0xFFFFFFFFu, t2, off);
    if (lane == 0) s.Ssum = t2;
  }
  __syncthreads();

  // ---- top-p keep mask via parallel suffix scan ----
  {
    const float limit = 1.0f - s.topp;
    const float Ssum  = s.Ssum;
    const int   c     = (m + NT2 - 1) / NT2;   // <= 4
    float ch[4]; float csum = 0.0f;
#pragma unroll
    for (int i = 0; i < 4; i++) {
      float e = 0.0f;
      if (i < c) {
        int r = tid * c + i;
        if (r < m) e = eArr[m - 1 - r] / Ssum;
      }
      ch[i] = e; csum += e;
    }
    float inc = csum;
    for (int off = 1; off < 32; off <<= 1) {
      float n = __shfl_up_sync(0xFFFFFFFFu, inc, off);
      if (lane >= off) inc += n;
    }
    float wexcl = inc - csum;
    if (lane == 31) s.red[wid] = inc;
    __syncthreads();
    if (wid == 0) {
      float wv = s.red[lane];
      float wi = wv;
      for (int off = 1; off < 32; off <<= 1) {
        float n = __shfl_up_sync(0xFFFFFFFFu, wi, off);
        if (lane >= off) wi += n;
      }
      s.red[lane] = wi - wv;
    }
    __syncthreads();
    float base2 = s.red[wid] + wexcl;
    float run = 0.0f;
#pragma unroll
    for (int i = 0; i < 4; i++) {
      if (i < c) {
        int r = tid * c + i;
        run += ch[i];
        if (r < m) {
          int jj = m - 1 - r;
          float T = base2 + run;
          keepArr[jj] = (jj == 0 || T > limit) ? 1u : 0u;
        }
      }
    }
  }
  __syncthreads();

  // ---- gumbel argmax over kept survivors ----
  for (int jj = tid; jj < m; jj += NT2) {
    if (keepArr[jj]) {
      uint32_t idxc = (uint32_t)(act[jj] & 0xFFFFFFFFull);
      int v = (int)(~idxc);
      float vj = funmap((uint32_t)(act[jj] >> 32));
      float g  = gumbel_jax((uint32_t)(b * V + v));
      float cand = vj + g;
      unsigned long long key = ((unsigned long long)fmap(cand) << 32) | (uint32_t)(~(uint32_t)v);
      atomicMax(&s.bestKey, key);
    }
  }
  __syncthreads();

  if (tid == 0) {
    int greedy  = (int)(~(uint32_t)(act[0] & 0xFFFFFFFFull));
    int randomS = (int)(~(uint32_t)(s.bestKey & 0xFFFFFFFFull));
    int sampled = (s.temp < 1e-5f) ? greedy : randomS;
    out[b] = (float)sampled;
  }
}

extern "C" void kernel_launch(void* const* d_in, const int* in_sizes, int n_in,
                              void* d_out, int out_size) {
  const float* logits      = (const float*)d_in[0];
  const float* temperature = (const float*)d_in[1];
  const float* presence    = (const float*)d_in[2];
  const float* frequency   = (const float*)d_in[3];
  const float* repetition  = (const float*)d_in[4];
  const float* top_p       = (const float*)d_in[5];
  const int*   prompt_ids  = (const int*)d_in[6];
  const int*   output_ids  = (const int*)d_in[7];
  const int*   output_lens = (const int*)d_in[8];
  const int*   stop_ids    = (const int*)d_in[9];
  const int*   min_tokens  = (const int*)d_in[10];
  const int*   top_k       = (const int*)d_in[11];
  const int*   mnl_ptr     = (n_in >= 13) ? (const int*)d_in[12] : nullptr;

  const int B = in_sizes[1];
  const int V = in_sizes[0] / B;
  const int P = in_sizes[6] / B;
  const int O = in_sizes[7] / B;
  const int nStop = in_sizes[9] / B;

  int nF4 = V >> 2;
  int nQ  = nF4 / SPLIT;
  int tokLast = V - (SPLIT - 1) * (nQ << 2);
  int tokMax  = (nQ << 2) > tokLast ? (nQ << 2) : tokLast;
  int cntWords = (tokMax + 3) >> 2;
  int pbW      = (tokMax + 31) >> 5;
  int words1 = cntWords + pbW + 2 * NBINS;
  if (words1 & 1) words1++;
  size_t smem1 = (size_t)words1 * 4 + (size_t)(CAPA + CAPB) * 8;
  size_t smem2 = (size_t)(MAXCAND + CAPC + CAPBC) * 8;

  cudaFuncSetAttribute(sampler_pass1, cudaFuncAttributeMaxDynamicSharedMemorySize, (int)smem1);
  cudaFuncSetAttribute(sampler_pass2, cudaFuncAttributeMaxDynamicSharedMemorySize, (int)smem2);

  sampler_pass1<<<B * SPLIT, NT1, smem1>>>(
      logits, temperature, presence, frequency, repetition,
      prompt_ids, output_ids, output_lens, stop_ids, min_tokens, top_k,
      mnl_ptr, B, V, P, O, nStop);
  sampler_pass2<<<B, NT2, smem2>>>(
      temperature, top_p, top_k, mnl_ptr, (float*)d_out, B, V);
}

// round 16
// speedup vs baseline: 1.4925x; 1.4925x over previous
#include <cuda_runtime.h>
#include <cstdint>
#include <math.h>

#define NEG_INF   (-3.4028234663852886e38f)
#define NBINS     4096
#define CAPA      2048
#define CAPB      1024
#define CAPP      4096
#define CAPC      4096
#define CAPBF     2048
#define CAPS      512
#define CAPSB     256
#define SPLIT     4
#define NT1       512
#define NT2       1024
#define MAXCTAS   1024

// cross-kernel scratch (static __device__ — allocation-free)
__device__ float g_expsum[MAXCTAS];
__device__ int   g_nA[MAXCTAS];
__device__ int   g_nB[MAXCTAS];
__device__ unsigned long long g_candA[(size_t)MAXCTAS * CAPA];
__device__ unsigned long long g_candB[(size_t)MAXCTAS * CAPB];

// monotone float <-> uint32 mapping (total order)
__device__ __forceinline__ uint32_t fmap(float f) {
  uint32_t u = __float_as_uint(f);
  return u ^ ((u & 0x80000000u) ? 0xFFFFFFFFu : 0x80000000u);
}
__device__ __forceinline__ float funmap(uint32_t u) {
  uint32_t b = (u & 0x80000000u) ? (u ^ 0x80000000u) : ~u;
  return __uint_as_float(b);
}

struct Ctl1 {
  float rep, rcpRep, rcpTemp, freq, pres;
  int   nStop, hasStop;
  int   stop[8];
  int   kk, mnl;
  int   binSel, nA, nB, nPend;
  uint32_t thrA;
  float tBf, tRejf;
  float red[32];
  uint32_t chunk[64];
};

__device__ __forceinline__ float proc_cp(float raw, int v, int cnt, int pb, const Ctl1& s) {
  float x = raw;
  if (s.hasStop) {
#pragma unroll
    for (int i = 0; i < 8; i++)
      if (i < s.nStop && v == s.stop[i]) x = NEG_INF;
  }
  bool outm = cnt > 0;
  bool seen = outm || (pb != 0);
  float scale = seen ? ((x > 0.0f) ? s.rcpRep : s.rep) : 1.0f;
  x = x * scale;
  x = x - s.freq * (float)cnt;
  if (outm) x = x - s.pres;
  return x * s.rcpTemp;
}

// largest bin beta with (#subset elements in bins >= beta) >= need
template<typename CTL>
__device__ int select_bin(const uint32_t* hist, int need, CTL& s) {
  if (threadIdx.x < 64) {
    uint32_t sum = 0;
    int base = (int)threadIdx.x << 6;
    for (int i = 0; i < 64; i++) sum += hist[base + i];
    s.chunk[threadIdx.x] = sum;
  }
  __syncthreads();
  if (threadIdx.x == 0) {
    long long acc = 0;
    int bin = 0;
    for (int c = 63; c >= 0; c--) {
      long long nacc = acc + (long long)s.chunk[c];
      if (nacc >= need) {
        long long a2 = acc;
        bin = c << 6;
        for (int bi = (c << 6) + 63; bi >= (c << 6); bi--) {
          a2 += (long long)hist[bi];
          if (a2 >= need) { bin = bi; break; }
        }
        break;
      }
      acc = nacc;
    }
    s.binSel = bin;
  }
  __syncthreads();
  return s.binSel;
}

template<int NT>
__device__ void bitonic_desc(unsigned long long* a, int n) {
  for (int k = 2; k <= n; k <<= 1) {
    for (int j = k >> 1; j > 0; j >>= 1) {
      __syncthreads();
      for (int i = (int)threadIdx.x; i < n; i += NT) {
        int l = i ^ j;
        if (l > i) {
          unsigned long long ai = a[i], al = a[l];
          bool descSeg = ((i & k) == 0);
          bool doSwap = descSeg ? (ai < al) : (ai > al);
          if (doSwap) { a[i] = al; a[l] = ai; }
        }
      }
    }
  }
  __syncthreads();
}

// Threefry-2x32-20, JAX partitionable counter mode, key (0,42); out = out0^out1.
__device__ __forceinline__ float gumbel_jax(uint32_t idx) {
  uint32_t x0 = 0u, x1 = idx;
  const uint32_t k0 = 0u, k1 = 42u;
  const uint32_t k2 = k0 ^ k1 ^ 0x1BD11BDAu;
  x0 += k0; x1 += k1;
#define TFR(r) { x0 += x1; x1 = __funnelshift_l(x1, x1, (r)); x1 ^= x0; }
  TFR(13) TFR(15) TFR(26) TFR(6)   x0 += k1; x1 += k2 + 1u;
  TFR(17) TFR(29) TFR(16) TFR(24)  x0 += k2; x1 += k0 + 2u;
  TFR(13) TFR(15) TFR(26) TFR(6)   x0 += k0; x1 += k1 + 3u;
  TFR(17) TFR(29) TFR(16) TFR(24)  x0 += k1; x1 += k2 + 4u;
  TFR(13) TFR(15) TFR(26) TFR(6)   x0 += k2; x1 += k0 + 5u;
#undef TFR
  uint32_t bits = x0 ^ x1;
  float x = __uint_as_float((bits >> 9) | 0x3F800000u) - 1.0f;
  float u = fmaxf(1e-10f, x + 1e-10f);
  return -logf(-logf(u));
}

// ============================================================================
// Kernel 1: per quarter-row (R15 with chunk = 1/16 of quarter)
// ============================================================================
__global__ __launch_bounds__(NT1, 2)
void sampler_pass1(const float* __restrict__ logits,
                   const float* __restrict__ temperature,
                   const float* __restrict__ presence,
                   const float* __restrict__ frequency,
                   const float* __restrict__ repetition,
                   const int*   __restrict__ prompt_ids,
                   const int*   __restrict__ output_ids,
                   const int*   __restrict__ output_lens,
                   const int*   __restrict__ stop_ids,
                   const int*   __restrict__ min_tokens,
                   const int*   __restrict__ top_k,
                   const int*   __restrict__ mnl_ptr,
                   int B, int V, int P, int O, int nStopIn) {
  extern __shared__ uint32_t dsm[];
  __shared__ Ctl1 s;

  const int cta  = blockIdx.x;
  const int b    = cta / SPLIT;
  const int h    = cta % SPLIT;
  const int tid  = (int)threadIdx.x;
  const int lane = tid & 31;
  const int wid  = tid >> 5;

  const int nF4 = V >> 2;
  const int nQ  = nF4 / SPLIT;
  const int qLo = h * nQ;
  const int qHi = (h == SPLIT - 1) ? nF4 : qLo + nQ;
  const int nQl = qHi - qLo;
  const int vLo = qLo << 2;
  const int vHi = (h == SPLIT - 1) ? V : (qHi << 2);
  const int nTok = vHi - vLo;

  const int cntWords = (nTok + 3) >> 2;
  const int pbW      = (nTok + 31) >> 5;
  uint32_t* cntW  = dsm;
  uint32_t* pbits = cntW + cntWords;
  uint32_t* histR = pbits + pbW;
  uint32_t* histP = histR + NBINS;
  int wordsBefore = cntWords + pbW + 2 * NBINS;
  if (wordsBefore & 1) wordsBefore++;
  unsigned long long* candA = (unsigned long long*)(dsm + wordsBefore);
  unsigned long long* candB = candA + CAPA;
  uint32_t* pend = histP;

  for (int i = tid; i < cntWords; i += NT1) cntW[i] = 0u;
  for (int i = tid; i < pbW;      i += NT1) pbits[i] = 0u;
  for (int i = tid; i < NBINS;    i += NT1) { histP[i] = 0u; histR[i] = 0u; }
  if (tid == 0) {
    s.nA = 0; s.nB = 0; s.nPend = 0;
    float temp = temperature[b];
    float tempEff = (temp < 1e-5f) ? 1.0f : temp;
    s.rep    = repetition[b];
    s.rcpRep = 1.0f / s.rep;
    s.rcpTemp = 1.0f / tempEff;
    s.freq = frequency[b];
    s.pres = presence[b];
    int ol  = output_lens[b];
    int pen = (ol < min_tokens[b]) ? 1 : 0;
    int ns  = nStopIn > 8 ? 8 : nStopIn;
    s.nStop   = ns;
    s.hasStop = (pen && ns > 0) ? 1 : 0;
    for (int i = 0; i < ns; i++) s.stop[i] = pen ? stop_ids[b * nStopIn + i] : -1;
    s.kk  = top_k[b];
    s.mnl = mnl_ptr ? mnl_ptr[0] : 20;
  }
  __syncthreads();

  for (int i = tid; i < P; i += NT1) {
    int t = prompt_ids[(size_t)b * P + i];
    if (t >= vLo && t < vHi) {
      int tl = t - vLo;
      atomicOr(&pbits[tl >> 5], 1u << (tl & 31));
    }
  }
  {
    int ol = output_lens[b];
    for (int i = tid; i < O; i += NT1) {
      if (i < ol) {
        int t = output_ids[(size_t)b * O + i];
        if (t >= vLo && t < vHi) {
          int tl = t - vLo;
          atomicAdd(&cntW[tl >> 2], 1u << ((tl & 3) * 8));
        }
      }
    }
  }
  __syncthreads();

  const float* rowL = logits + (size_t)b * V;
  const float4* row4 = (const float4*)rowL;
  int CH = nQl >> 4;            // chunk = 1/16 of quarter
  if (CH < 1) CH = nQl;
  float a0 = 0.f, a1 = 0.f, a2 = 0.f, a3 = 0.f;
  float b0 = 0.f, b1 = 0.f, b2 = 0.f, b3 = 0.f;

  for (int jl = tid; jl < CH; jl += NT1) {
    float4 f = row4[qLo + jl];
    a0 += __expf(f.x); a1 += __expf(f.y);
    a2 += __expf(f.z); a3 += __expf(f.w);
    uint32_t cw = cntW[jl];
    uint32_t pw = pbits[jl >> 3];
    float vals[4] = {f.x, f.y, f.z, f.w};
#pragma unroll
    for (int q = 0; q < 4; q++) {
      int v = ((qLo + jl) << 2) + q;
      int cnt = (int)((cw >> (q * 8)) & 0xFFu);
      int pb  = (int)((pw >> (((jl & 7) << 2) + q)) & 1u);
      float px = proc_cp(vals[q], v, cnt, pb, s);
      atomicAdd(&histR[fmap(vals[q]) >> 20], 1u);
      atomicAdd(&histP[fmap(px)      >> 20], 1u);
    }
  }
  __syncthreads();

  int kneed = s.kk; if (kneed < 1) kneed = 1; if (kneed > V) kneed = V;
  int binA = select_bin(histP, kneed, s);
  int mnl  = s.mnl;
  int binR = select_bin(histR, mnl, s);

  if (tid == 0) {
    s.thrA = (uint32_t)binA << 20;
    s.tBf  = funmap((uint32_t)binR << 20);
    float tA = funmap(s.thrA);
    float rejf = -INFINITY;
    if (tA > 0.0f && s.rep >= 1.0f && s.freq >= 0.0f && s.pres >= 0.0f) {
      float tempEff = 1.0f / s.rcpTemp;
      float rr = tA * tempEff * 0.99f;
      if (rr > 0.0f) rejf = rr;
    }
    s.tRejf = rejf;
  }
  __syncthreads();
  const float tBf   = s.tBf;
  const float tRejf = s.tRejf;
  const float tMin  = fminf(tBf, tRejf);
  uint32_t thrA = s.thrA;

  auto check4 = [&](float4 f, int jl) {
    float vals[4] = {f.x, f.y, f.z, f.w};
#pragma unroll
    for (int q = 0; q < 4; q++) {
      float raw = vals[q];
      int v = ((qLo + jl) << 2) + q;
      if (raw >= tBf) {
        int p = atomicAdd(&s.nB, 1);
        if (p < CAPB) candB[p] = ((unsigned long long)fmap(raw) << 32) | (uint32_t)(~(uint32_t)v);
      }
      if (raw >= tRejf) {
        uint32_t cw = cntW[jl];
        uint32_t pw = pbits[jl >> 3];
        int cnt = (int)((cw >> (q * 8)) & 0xFFu);
        int pb  = (int)((pw >> (((jl & 7) << 2) + q)) & 1u);
        float px = proc_cp(raw, v, cnt, pb, s);
        uint32_t mp = fmap(px);
        if (mp >= thrA) {
          int p = atomicAdd(&s.nA, 1);
          if (p < CAPA) candA[p] = ((unsigned long long)mp << 32) | (uint32_t)(~(uint32_t)v);
        }
      }
    }
  };
  auto push_pend = [&](float4 f, int jl) {
    int p = atomicAdd(&s.nPend, 1);
    if (p < CAPP) pend[p] = (uint32_t)jl;
    else          check4(f, jl);
  };

  int jl = CH + tid;
  for (; jl + 3 * NT1 < nQl; jl += 4 * NT1) {
    float4 f0 = row4[qLo + jl];
    float4 f1 = row4[qLo + jl + NT1];
    float4 f2 = row4[qLo + jl + 2 * NT1];
    float4 f3 = row4[qLo + jl + 3 * NT1];
    a0 += __expf(f0.x); a1 += __expf(f0.y); a2 += __expf(f0.z); a3 += __expf(f0.w);
    b0 += __expf(f1.x); b1 += __expf(f1.y); b2 += __expf(f1.z); b3 += __expf(f1.w);
    a0 += __expf(f2.x); a1 += __expf(f2.y); a2 += __expf(f2.z); a3 += __expf(f2.w);
    b0 += __expf(f3.x); b1 += __expf(f3.y); b2 += __expf(f3.z); b3 += __expf(f3.w);
    float mx0 = fmaxf(fmaxf(f0.x, f0.y), fmaxf(f0.z, f0.w));
    float mx1 = fmaxf(fmaxf(f1.x, f1.y), fmaxf(f1.z, f1.w));
    float mx2 = fmaxf(fmaxf(f2.x, f2.y), fmaxf(f2.z, f2.w));
    float mx3 = fmaxf(fmaxf(f3.x, f3.y), fmaxf(f3.z, f3.w));
    if (mx0 >= tMin) push_pend(f0, jl);
    if (mx1 >= tMin) push_pend(f1, jl + NT1);
    if (mx2 >= tMin) push_pend(f2, jl + 2 * NT1);
    if (mx3 >= tMin) push_pend(f3, jl + 3 * NT1);
  }
  for (; jl < nQl; jl += NT1) {
    float4 f = row4[qLo + jl];
    a0 += __expf(f.x); a1 += __expf(f.y);
    a2 += __expf(f.z); a3 += __expf(f.w);
    float mx = fmaxf(fmaxf(f.x, f.y), fmaxf(f.z, f.w));
    if (mx >= tMin) push_pend(f, jl);
  }
  for (int jc = tid; jc < CH; jc += NT1) {
    float4 f = row4[qLo + jc];
    float mx = fmaxf(fmaxf(f.x, f.y), fmaxf(f.z, f.w));
    if (mx >= tMin) push_pend(f, jc);
  }
  for (int v = (qHi << 2) + tid; v < vHi; v += NT1) {
    float raw = rowL[v];
    a0 += __expf(raw);
    int tl = v - vLo;
    if (raw >= tBf) {
      int p = atomicAdd(&s.nB, 1);
      if (p < CAPB) candB[p] = ((unsigned long long)fmap(raw) << 32) | (uint32_t)(~(uint32_t)v);
    }
    if (raw >= tRejf) {
      uint32_t cw = cntW[tl >> 2];
      uint32_t pw = pbits[tl >> 5];
      int cnt = (int)((cw >> ((tl & 3) * 8)) & 0xFFu);
      int pb  = (int)((pw >> (tl & 31)) & 1u);
      float px = proc_cp(raw, v, cnt, pb, s);
      uint32_t mp = fmap(px);
      if (mp >= thrA) {
        int p = atomicAdd(&s.nA, 1);
        if (p < CAPA) candA[p] = ((unsigned long long)mp << 32) | (uint32_t)(~(uint32_t)v);
      }
    }
  }
  __syncthreads();

  {
    int np = s.nPend < CAPP ? s.nPend : CAPP;
    for (int i = tid; i < np; i += NT1) {
      int jj = (int)pend[i];
      check4(row4[qLo + jj], jj);
    }
  }

  {
    float sl = ((a0 + a1) + (a2 + a3)) + ((b0 + b1) + (b2 + b3));
    for (int off = 16; off; off >>= 1) sl += __shfl_down_sync(0xFFFFFFFFu, sl, off);
    if (lane == 0) s.red[wid] = sl;
  }
  __syncthreads();
  if (wid == 0) {
    float t2 = (lane < (NT1 / 32)) ? s.red[lane] : 0.0f;
    for (int off = 16; off; off >>= 1) t2 += __shfl_down_sync(0xFFFFFFFFu, t2, off);
    if (lane == 0) g_expsum[cta] = t2;
  }
  __syncthreads();

  while (s.nA > CAPA) {
    __syncthreads();
    if (tid == 0) { binA = binA < 4095 ? binA + 1 : 4095; s.thrA = (uint32_t)binA << 20; s.nA = 0; }
    __syncthreads();
    binA = (int)(s.thrA >> 20);
    thrA = s.thrA;
    for (int v = vLo + tid; v < vHi; v += NT1) {
      float raw = rowL[v];
      if (raw >= tRejf) {
        int tl = v - vLo;
        uint32_t cw = cntW[tl >> 2];
        uint32_t pw = pbits[tl >> 5];
        int cnt = (int)((cw >> ((tl & 3) * 8)) & 0xFFu);
        int pb  = (int)((pw >> (tl & 31)) & 1u);
        float px = proc_cp(raw, v, cnt, pb, s);
        uint32_t mp = fmap(px);
        if (mp >= thrA) {
          int p = atomicAdd(&s.nA, 1);
          if (p < CAPA) candA[p] = ((unsigned long long)mp << 32) | (uint32_t)(~(uint32_t)v);
        }
      }
    }
    __syncthreads();
    if (binA >= 4095) break;
  }
  __syncthreads();

  int nAc = s.nA < CAPA ? s.nA : CAPA;
  int nBc = s.nB < CAPB ? s.nB : CAPB;
  if (tid == 0) { g_nA[cta] = nAc; g_nB[cta] = nBc; }
  for (int i = tid; i < nAc; i += NT1) g_candA[(size_t)cta * CAPA + i] = candA[i];
  for (int i = tid; i < nBc; i += NT1) g_candB[(size_t)cta * CAPB + i] = candB[i];
}

// ============================================================================
// Kernel 2: per row — two-level histogram refinement, tiny sorts, epilogue
// ============================================================================
struct Ctl2 {
  float temp, topp, Ssum, lse;
  int   kk, mnl, nAtot, nBtot, mCount;
  int   binSel, cntAbove, nS, nF;
  unsigned long long bestKey;
  float red[32];
  uint32_t chunk[64];
  int   na[SPLIT], nb[SPLIT];
};

__global__ __launch_bounds__(NT2, 1)
void sampler_pass2(const float* __restrict__ temperature,
                   const float* __restrict__ top_p,
                   const int*   __restrict__ top_k,
                   const int*   __restrict__ mnl_ptr,
                   float*       __restrict__ out,
                   int B, int V) {
  extern __shared__ uint32_t dsm[];
  __shared__ Ctl2 s;

  const int b    = blockIdx.x;
  const int base = b * SPLIT;
  const int tid  = (int)threadIdx.x;
  const int lane = tid & 31;
  const int wid  = tid >> 5;

  unsigned long long* candC  = (unsigned long long*)dsm;    // CAPC  (A fallback)
  unsigned long long* candBF = candC + CAPC;                // CAPBF (B fallback)
  unsigned long long* candS  = candBF + CAPBF;              // CAPS  (A small)
  unsigned long long* candSB = candS + CAPS;                // CAPSB (B small)
  uint32_t* hist    = (uint32_t*)(candSB + CAPSB);          // NBINS (then eArr)
  uint32_t* keepBuf = hist + NBINS;                         // NBINS

  if (tid == 0) {
    int oa = 0, ob = 0;
    for (int i = 0; i < SPLIT; i++) {
      s.na[i] = g_nA[base + i]; oa += s.na[i];
      s.nb[i] = g_nB[base + i]; ob += s.nb[i];
    }
    s.nAtot = oa; s.nBtot = ob;
    float es = 0.0f;
    for (int i = 0; i < SPLIT; i++) es += g_expsum[base + i];
    s.lse  = logf(es);
    s.temp = temperature[b];
    s.topp = top_p[b];
    s.kk   = top_k[b];
    s.mnl  = mnl_ptr ? mnl_ptr[0] : 20;
    s.bestKey = 0ull;
  }
  __syncthreads();
  const int mnl = s.mnl;
  int kneed = s.kk; if (kneed < 1) kneed = 1; if (kneed > V) kneed = V;
  const int nAtot = s.nAtot, nBtot = s.nBtot;

  // generic two-level select + compact; returns active buffer & count
  auto twolevel = [&](const unsigned long long* gbase, const int* cnts, int stride,
                      int need, unsigned long long* smallBuf, int capSmall,
                      unsigned long long* fbBuf, int capFb,
                      unsigned long long*& act, int& nAct) {
    // level-1 histogram
    for (int i = tid; i < NBINS; i += NT2) hist[i] = 0u;
    __syncthreads();
    for (int i = 0; i < SPLIT; i++) {
      int n = cnts[i];
      const unsigned long long* src = gbase + (size_t)i * stride;
      for (int idx = tid; idx < n; idx += NT2)
        atomicAdd(&hist[(uint32_t)(src[idx] >> 52)], 1u);
    }
    __syncthreads();
    int sel1 = select_bin(hist, need, s);
    // countAbove = sum hist[sel1+1..]
    if (tid == 0) s.cntAbove = 0;
    __syncthreads();
    {
      uint32_t loc = 0;
      for (int i = sel1 + 1 + tid; i < NBINS; i += NT2) loc += hist[i];
      for (int off = 16; off; off >>= 1) loc += __shfl_down_sync(0xFFFFFFFFu, loc, off);
      if (lane == 0 && loc) atomicAdd((unsigned*)&s.cntAbove, loc);
    }
    __syncthreads();
    int cAbove = s.cntAbove;
    int need2 = need - cAbove; if (need2 < 1) need2 = 1;
    // level-2 histogram (bits [40,52) of keys within sel1)
    for (int i = tid; i < NBINS; i += NT2) hist[i] = 0u;
    __syncthreads();
    for (int i = 0; i < SPLIT; i++) {
      int n = cnts[i];
      const unsigned long long* src = gbase + (size_t)i * stride;
      for (int idx = tid; idx < n; idx += NT2) {
        unsigned long long key = src[idx];
        if ((int)(uint32_t)(key >> 52) == sel1)
          atomicAdd(&hist[(uint32_t)(key >> 40) & 0xFFFu], 1u);
      }
    }
    __syncthreads();
    int sel2 = select_bin(hist, need2, s);
    // two-level compact
    if (tid == 0) s.nS = 0;
    __syncthreads();
    for (int i = 0; i < SPLIT; i++) {
      int n = cnts[i];
      const unsigned long long* src = gbase + (size_t)i * stride;
      for (int idx = tid; idx < n; idx += NT2) {
        unsigned long long key = src[idx];
        int b1 = (int)(uint32_t)(key >> 52);
        int b2 = (int)((uint32_t)(key >> 40) & 0xFFFu);
        if (b1 > sel1 || (b1 == sel1 && b2 >= sel2)) {
          int p = atomicAdd(&s.nS, 1);
          if (p < capSmall) smallBuf[p] = key;
        }
      }
    }
    __syncthreads();
    int nS = s.nS;
    if (nS <= capSmall) {
      int n = nS < 1 ? 1 : nS;
      int sortN = 2; while (sortN < n) sortN <<= 1;
      for (int i = n + tid; i < sortN; i += NT2) smallBuf[i] = 0ull;
      __syncthreads();
      bitonic_desc<NT2>(smallBuf, sortN);
      act = smallBuf; nAct = n;
    } else {  // fallback: level-1 compact + sort (practically unreachable)
      if (tid == 0) s.nF = 0;
      __syncthreads();
      for (int i = 0; i < SPLIT; i++) {
        int n = cnts[i];
        const unsigned long long* src = gbase + (size_t)i * stride;
        for (int idx = tid; idx < n; idx += NT2) {
          unsigned long long key = src[idx];
          if ((int)(uint32_t)(key >> 52) >= sel1) {
            int p = atomicAdd(&s.nF, 1);
            if (p < capFb) fbBuf[p] = key;
          }
        }
      }
      __syncthreads();
      int nF = s.nF < capFb ? s.nF : capFb;
      if (nF < 1) nF = 1;
      int sortN = 2; while (sortN < nF) sortN <<= 1;
      for (int i = nF + tid; i < sortN; i += NT2) fbBuf[i] = 0ull;
      __syncthreads();
      bitonic_desc<NT2>(fbBuf, sortN);
      act = fbBuf; nAct = nF;
    }
  };

  // ---- A side ----
  unsigned long long* actA; int nActA;
  {
    int needA = kneed < nAtot ? kneed : nAtot; if (needA < 1) needA = 1;
    twolevel(&g_candA[(size_t)base * CAPA], s.na, CAPA, needA,
             candS, CAPS, candC, CAPC, actA, nActA);
  }
  // ---- B side ----
  unsigned long long* actB; int nActB;
  {
    int needB = mnl < nBtot ? mnl : nBtot; if (needB < 1) needB = 1;
    twolevel(&g_candB[(size_t)base * CAPB], s.nb, CAPB, needB,
             candSB, CAPSB, candBF, CAPBF, actB, nActB);
  }

  // ---- outputs 1 & 2 (topk logprobs / indices) ----
  {
    int lim = nActB < nBtot ? nActB : nBtot;
    for (int j = tid; j < mnl; j += NT2) {
      float val; int v;
      if (j < lim) {
        unsigned long long key = actB[j];
        v   = (int)(~(uint32_t)(key & 0xFFFFFFFFull));
        val = funmap((uint32_t)(key >> 32));
      } else { v = 0; val = NEG_INF; }
      out[(size_t)B + (size_t)b * mnl + j]                   = val - s.lse;
      out[(size_t)B + (size_t)B * mnl + (size_t)b * mnl + j] = (float)v;
    }
  }

  // ---- top-k boundary + survivor count ----
  if (tid == 0) {
    int k = kneed; if (k > nActA) k = nActA; if (k < 1) k = 1;
    uint32_t kth = (uint32_t)(actA[k - 1] >> 32);
    int m = k;
    while (m < nActA && (uint32_t)(actA[m] >> 32) >= kth) m++;
    if (m > CAPC) m = CAPC;
    s.mCount = m;
  }
  __syncthreads();
  const int m = s.mCount;
  const float maxV = funmap((uint32_t)(actA[0] >> 32));

  float*    eArr    = (float*)hist;      // hist free after selection
  uint32_t* keepArr = keepBuf;

  // ---- softmax over survivors ----
  float local = 0.0f;
  for (int jj = tid; jj < m; jj += NT2) {
    float vj = funmap((uint32_t)(actA[jj] >> 32));
    float e  = expf(vj - maxV);
    eArr[jj] = e;
    local += e;
  }
  for (int off = 16; off; off >>= 1) local += __shfl_down_sync(0xFFFFFFFFu, local, off);
  if (lane == 0) s.red[wid] = local;
  __syncthreads();
  if (wid == 0) {
    float t2 = s.red[lane];
    for (int off = 16; off; off >>= 1) t2 += __shfl_down_sync(0xFFFFFFFFu, t2, off);
    if (lane == 0) s.Ssum = t2;
  }
  __syncthreads();

  // ---- top-p keep mask via parallel suffix scan ----
  {
    const float limit = 1.0f - s.topp;
    const float Ssum  = s.Ssum;
    const int   c     = (m + NT2 - 1) / NT2;   // <= 4
    float ch[4]; float csum = 0.0f;
#pragma unroll
    for (int i = 0; i < 4; i++) {
      float e = 0.0f;
      if (i < c) {
        int r = tid * c + i;
        if (r < m) e = eArr[m - 1 - r] / Ssum;
      }
      ch[i] = e; csum += e;
    }
    float inc = csum;
    for (int off = 1; off < 32; off <<= 1) {
      float n = __shfl_up_sync(0xFFFFFFFFu, inc, off);
      if (lane >= off) inc += n;
    }
    float wexcl = inc - csum;
    if (lane == 31) s.red[wid] = inc;
    __syncthreads();
    if (wid == 0) {
      float wv = s.red[lane];
      float wi = wv;
      for (int off = 1; off < 32; off <<= 1) {
        float n = __shfl_up_sync(0xFFFFFFFFu, wi, off);
        if (lane >= off) wi += n;
      }
      s.red[lane] = wi - wv;
    }
    __syncthreads();
    float base2 = s.red[wid] + wexcl;
    float run = 0.0f;
#pragma unroll
    for (int i = 0; i < 4; i++) {
      if (i < c) {
        int r = tid * c + i;
        run += ch[i];
        if (r < m) {
          int jj = m - 1 - r;
          float T = base2 + run;
          keepArr[jj] = (jj == 0 || T > limit) ? 1u : 0u;
        }
      }
    }
  }
  __syncthreads();

  // ---- gumbel argmax over kept survivors ----
  for (int jj = tid; jj < m; jj += NT2) {
    if (keepArr[jj]) {
      uint32_t idxc = (uint32_t)(actA[jj] & 0xFFFFFFFFull);
      int v = (int)(~idxc);
      float vj = funmap((uint32_t)(actA[jj] >> 32));
      float g  = gumbel_jax((uint32_t)(b * V + v));
      float cand = vj + g;
      unsigned long long key = ((unsigned long long)fmap(cand) << 32) | (uint32_t)(~(uint32_t)v);
      atomicMax(&s.bestKey, key);
    }
  }
  __syncthreads();

  if (tid == 0) {
    int greedy  = (int)(~(uint32_t)(actA[0] & 0xFFFFFFFFull));
    int randomS = (int)(~(uint32_t)(s.bestKey & 0xFFFFFFFFull));
    int sampled = (s.temp < 1e-5f) ? greedy : randomS;
    out[b] = (float)sampled;
  }
}

extern "C" void kernel_launch(void* const* d_in, const int* in_sizes, int n_in,
                              void* d_out, int out_size) {
  const float* logits      = (const float*)d_in[0];
  const float* temperature = (const float*)d_in[1];
  const float* presence    = (const float*)d_in[2];
  const float* frequency   = (const float*)d_in[3];
  const float* repetition  = (const float*)d_in[4];
  const float* top_p       = (const float*)d_in[5];
  const int*   prompt_ids  = (const int*)d_in[6];
  const int*   output_ids  = (const int*)d_in[7];
  const int*   output_lens = (const int*)d_in[8];
  const int*   stop_ids    = (const int*)d_in[9];
  const int*   min_tokens  = (const int*)d_in[10];
  const int*   top_k       = (const int*)d_in[11];
  const int*   mnl_ptr     = (n_in >= 13) ? (const int*)d_in[12] : nullptr;

  const int B = in_sizes[1];
  const int V = in_sizes[0] / B;
  const int P = in_sizes[6] / B;
  const int O = in_sizes[7] / B;
  const int nStop = in_sizes[9] / B;

  int nF4 = V >> 2;
  int nQ  = nF4 / SPLIT;
  int tokLast = V - (SPLIT - 1) * (nQ << 2);
  int tokMax  = (nQ << 2) > tokLast ? (nQ << 2) : tokLast;
  int cntWords = (tokMax + 3) >> 2;
  int pbW      = (tokMax + 31) >> 5;
  int words1 = cntWords + pbW + 2 * NBINS;
  if (words1 & 1) words1++;
  size_t smem1 = (size_t)words1 * 4 + (size_t)(CAPA + CAPB) * 8;
  size_t smem2 = (size_t)(CAPC + CAPBF + CAPS + CAPSB) * 8 + (size_t)(2 * NBINS) * 4;

  cudaFuncSetAttribute(sampler_pass1, cudaFuncAttributeMaxDynamicSharedMemorySize, (int)smem1);
  cudaFuncSetAttribute(sampler_pass2, cudaFuncAttributeMaxDynamicSharedMemorySize, (int)smem2);

  sampler_pass1<<<B * SPLIT, NT1, smem1>>>(
      logits, temperature, presence, frequency, repetition,
      prompt_ids, output_ids, output_lens, stop_ids, min_tokens, top_k,
      mnl_ptr, B, V, P, O, nStop);
  sampler_pass2<<<B, NT2, smem2>>>(
      temperature, top_p, top_k, mnl_ptr, (float*)d_out, B, V);
}